// round 10
// baseline (speedup 1.0000x reference)
#include <cuda_runtime.h>
#include <cuda_bf16.h>
#include <cstdint>

// HardBinaryVote: inputs [V=31, B=2,000,000] row-major {0,1} (int32 or f32 —
// vote == (bits != 0) either way); out[b] (FLOAT32) = majority = (2*ones > V).
//
// FINAL (roofline-converged): 1 uint4 column/thread, one-shot partition,
// 256-thread CTAs, __launch_bounds__(256,8) -> regs=32, 8 CTAs/SM resident,
// .cs streaming loads/stores, V=31 fully unrolled with dual accumulation
// chains (odd row peeled). Measured at the B300 LTS chip cap (~6.3 TB/s,
// path-independent); traffic (248 MB + 8 MB) is irreducible -> ~40 us kernel.

static constexpr int THREADS = 256;

template <int V>
__global__ __launch_bounds__(THREADS, 8)
void vote_vec4_final(const uint4* __restrict__ in4,
                     float4* __restrict__ out4,
                     int n4) {
    const int idx = blockIdx.x * THREADS + threadIdx.x;
    if (idx >= n4) return;

    const uint4* __restrict__ p = in4 + idx;

    int a0 = 0, a1 = 0, a2 = 0, a3 = 0;   // even-row chain
    int b0 = 0, b1 = 0, b2 = 0, b3 = 0;   // odd-row chain

    constexpr int VP = V & ~1;  // paired portion (30 for V=31)
#pragma unroll
    for (int v = 0; v < VP; v += 2) {
        uint4 x = __ldcs(&p[(long long)v * n4]);
        uint4 y = __ldcs(&p[(long long)(v + 1) * n4]);
        a0 += (x.x != 0u); a1 += (x.y != 0u);
        a2 += (x.z != 0u); a3 += (x.w != 0u);
        b0 += (y.x != 0u); b1 += (y.y != 0u);
        b2 += (y.z != 0u); b3 += (y.w != 0u);
    }
    if (V & 1) {
        uint4 x = __ldcs(&p[(long long)VP * n4]);
        a0 += (x.x != 0u); a1 += (x.y != 0u);
        a2 += (x.z != 0u); a3 += (x.w != 0u);
    }

    const int s0 = a0 + b0, s1 = a1 + b1, s2 = a2 + b2, s3 = a3 + b3;
    float4 o;
    o.x = (2 * s0 > V) ? 1.0f : 0.0f;
    o.y = (2 * s1 > V) ? 1.0f : 0.0f;
    o.z = (2 * s2 > V) ? 1.0f : 0.0f;
    o.w = (2 * s3 > V) ? 1.0f : 0.0f;
    __stcs(&out4[idx], o);
}

// Runtime-V vectorized fallback.
__global__ __launch_bounds__(THREADS)
void vote_vec4_dyn(const uint4* __restrict__ in4,
                   float4* __restrict__ out4,
                   int n4, int V) {
    const int idx = blockIdx.x * THREADS + threadIdx.x;
    if (idx >= n4) return;
    int s0 = 0, s1 = 0, s2 = 0, s3 = 0;
#pragma unroll 8
    for (int v = 0; v < V; v++) {
        uint4 x = __ldcs(&in4[(long long)v * n4 + idx]);
        s0 += (x.x != 0u); s1 += (x.y != 0u);
        s2 += (x.z != 0u); s3 += (x.w != 0u);
    }
    float4 o;
    o.x = (2 * s0 > V) ? 1.0f : 0.0f;
    o.y = (2 * s1 > V) ? 1.0f : 0.0f;
    o.z = (2 * s2 > V) ? 1.0f : 0.0f;
    o.w = (2 * s3 > V) ? 1.0f : 0.0f;
    __stcs(&out4[idx], o);
}

// Scalar fallback for B % 4 != 0.
__global__ __launch_bounds__(THREADS)
void vote_scalar(const unsigned int* __restrict__ in,
                 float* __restrict__ out,
                 int B, int V) {
    int b = blockIdx.x * THREADS + threadIdx.x;
    const int stride = gridDim.x * THREADS;
    for (; b < B; b += stride) {
        int s = 0;
        for (int v = 0; v < V; v++) s += (in[(long long)v * B + b] != 0u);
        out[b] = (2 * s > V) ? 1.0f : 0.0f;
    }
}

extern "C" void kernel_launch(void* const* d_in, const int* in_sizes, int n_in,
                              void* d_out, int out_size) {
    const unsigned int* in = (const unsigned int*)d_in[0];
    float* out = (float*)d_out;

    const long long Sin = in_sizes[0];
    long long B = out_size;
    if (B <= 0) return;
    long long V = (Sin % B == 0) ? (Sin / B) : 31;
    if (V <= 0) V = 1;

    if (B % 4 == 0) {
        const int n4 = (int)(B / 4);
        const int blocks = (n4 + THREADS - 1) / THREADS;
        if (V == 31) {
            vote_vec4_final<31><<<blocks, THREADS>>>(
                (const uint4*)in, (float4*)out, n4);
        } else {
            vote_vec4_dyn<<<blocks, THREADS>>>(
                (const uint4*)in, (float4*)out, n4, (int)V);
        }
    } else {
        int blocks = (int)((B + THREADS - 1) / THREADS);
        if (blocks > 148 * 32) blocks = 148 * 32;
        vote_scalar<<<blocks, THREADS>>>(in, out, (int)B, (int)V);
    }
}

// round 11
// speedup vs baseline: 1.0077x; 1.0077x over previous
#include <cuda_runtime.h>
#include <cuda_bf16.h>
#include <cstdint>

// HardBinaryVote: inputs [V=31, B=2,000,000] row-major {0,1} (int32 or f32 —
// vote == (bits != 0) either way); out[b] (FLOAT32) = majority = (2*ones > V).
//
// FINAL (roofline-converged): 1 uint4 column/thread, one-shot partition,
// 256-thread CTAs, __launch_bounds__(256,8) -> regs=32, 8 CTAs/SM resident,
// last-use (.lu) loads for read-once data + streaming (.cs) store, V=31 fully
// unrolled dual accumulation chains. Four schedules measured 6.28-6.37 TB/s:
// at the chip's streaming ceiling; traffic (248 MB + 8 MB) irreducible ->
// ~40 us kernel is the roofline.

static constexpr int THREADS = 256;

__device__ __forceinline__ uint4 ldlu4(const uint4* p) {
    return __ldlu(p);
}

template <int V>
__global__ __launch_bounds__(THREADS, 8)
void vote_vec4_final(const uint4* __restrict__ in4,
                     float4* __restrict__ out4,
                     int n4) {
    const int idx = blockIdx.x * THREADS + threadIdx.x;
    if (idx >= n4) return;

    const uint4* __restrict__ p = in4 + idx;

    int a0 = 0, a1 = 0, a2 = 0, a3 = 0;   // even-row chain
    int b0 = 0, b1 = 0, b2 = 0, b3 = 0;   // odd-row chain

    constexpr int VP = V & ~1;  // paired portion (30 for V=31)
#pragma unroll
    for (int v = 0; v < VP; v += 2) {
        uint4 x = ldlu4(&p[(long long)v * n4]);
        uint4 y = ldlu4(&p[(long long)(v + 1) * n4]);
        a0 += (x.x != 0u); a1 += (x.y != 0u);
        a2 += (x.z != 0u); a3 += (x.w != 0u);
        b0 += (y.x != 0u); b1 += (y.y != 0u);
        b2 += (y.z != 0u); b3 += (y.w != 0u);
    }
    if (V & 1) {
        uint4 x = ldlu4(&p[(long long)VP * n4]);
        a0 += (x.x != 0u); a1 += (x.y != 0u);
        a2 += (x.z != 0u); a3 += (x.w != 0u);
    }

    const int s0 = a0 + b0, s1 = a1 + b1, s2 = a2 + b2, s3 = a3 + b3;
    float4 o;
    o.x = (2 * s0 > V) ? 1.0f : 0.0f;
    o.y = (2 * s1 > V) ? 1.0f : 0.0f;
    o.z = (2 * s2 > V) ? 1.0f : 0.0f;
    o.w = (2 * s3 > V) ? 1.0f : 0.0f;
    __stcs(&out4[idx], o);
}

// Runtime-V vectorized fallback.
__global__ __launch_bounds__(THREADS)
void vote_vec4_dyn(const uint4* __restrict__ in4,
                   float4* __restrict__ out4,
                   int n4, int V) {
    const int idx = blockIdx.x * THREADS + threadIdx.x;
    if (idx >= n4) return;
    int s0 = 0, s1 = 0, s2 = 0, s3 = 0;
#pragma unroll 8
    for (int v = 0; v < V; v++) {
        uint4 x = __ldcs(&in4[(long long)v * n4 + idx]);
        s0 += (x.x != 0u); s1 += (x.y != 0u);
        s2 += (x.z != 0u); s3 += (x.w != 0u);
    }
    float4 o;
    o.x = (2 * s0 > V) ? 1.0f : 0.0f;
    o.y = (2 * s1 > V) ? 1.0f : 0.0f;
    o.z = (2 * s2 > V) ? 1.0f : 0.0f;
    o.w = (2 * s3 > V) ? 1.0f : 0.0f;
    __stcs(&out4[idx], o);
}

// Scalar fallback for B % 4 != 0.
__global__ __launch_bounds__(THREADS)
void vote_scalar(const unsigned int* __restrict__ in,
                 float* __restrict__ out,
                 int B, int V) {
    int b = blockIdx.x * THREADS + threadIdx.x;
    const int stride = gridDim.x * THREADS;
    for (; b < B; b += stride) {
        int s = 0;
        for (int v = 0; v < V; v++) s += (in[(long long)v * B + b] != 0u);
        out[b] = (2 * s > V) ? 1.0f : 0.0f;
    }
}

extern "C" void kernel_launch(void* const* d_in, const int* in_sizes, int n_in,
                              void* d_out, int out_size) {
    const unsigned int* in = (const unsigned int*)d_in[0];
    float* out = (float*)d_out;

    const long long Sin = in_sizes[0];
    long long B = out_size;
    if (B <= 0) return;
    long long V = (Sin % B == 0) ? (Sin / B) : 31;
    if (V <= 0) V = 1;

    if (B % 4 == 0) {
        const int n4 = (int)(B / 4);
        const int blocks = (n4 + THREADS - 1) / THREADS;
        if (V == 31) {
            vote_vec4_final<31><<<blocks, THREADS>>>(
                (const uint4*)in, (float4*)out, n4);
        } else {
            vote_vec4_dyn<<<blocks, THREADS>>>(
                (const uint4*)in, (float4*)out, n4, (int)V);
        }
    } else {
        int blocks = (int)((B + THREADS - 1) / THREADS);
        if (blocks > 148 * 32) blocks = 148 * 32;
        vote_scalar<<<blocks, THREADS>>>(in, out, (int)B, (int)V);
    }
}